// round 6
// baseline (speedup 1.0000x reference)
#include <cuda_runtime.h>

// 2-layer LSTM (B=2048, T=512, I=1, H=50) + FC(50->1).
// 128 persistent CTAs x 16 batch. 448 threads: thread = (k in [0,56),
// b in [0,4), half in {0,1}), handling 4 batches (b,b+4,b+8,b+12) and
// HALF the reduction dim (7 of 14 padded ull2 chunks). Halves sit in
// adjacent lanes; partial sums combined with shfl.xor(1) - no extra barrier.
// Layer-skewed: iteration u does L1(t=u) + L2(t=u-1), 1 syncthreads/step.
// Math: fma.rn.f32x2 on LDS.128.

#define HID   50
#define KP    56
#define BT    16
#define WS    56          // weight row stride (floats) = 14 x 16B
#define HS    56          // h row stride (floats)
#define NU2   14          // ull2 chunks per row
#define SXS   513         // x row stride (odd -> conflict-free)
#define NTH   448
#define SEQL  512
#define NBATCH 2048
#define HBUF  (BT * HS)
#define GS2   (KP * WS / 4)   // 784 ull2 between gate blocks

__device__ __forceinline__ float ftanh(float v) {
    float y;
    asm("tanh.approx.f32 %0, %1;" : "=f"(y) : "f"(v));
    return y;
}
__device__ __forceinline__ float fsigm(float v) {
    return fmaf(0.5f, ftanh(0.5f * v), 0.5f);
}
__device__ __forceinline__ void fma2(unsigned long long& d,
                                     unsigned long long a, unsigned long long b) {
    asm("fma.rn.f32x2 %0, %1, %2, %0;" : "+l"(d) : "l"(a), "l"(b));
}
// reduce packed pair + partner lane's partial -> full dot product
__device__ __forceinline__ float comb(unsigned long long d) {
    float lo, hi;
    asm("mov.b64 {%0, %1}, %2;" : "=f"(lo), "=f"(hi) : "l"(d));
    float s = lo + hi;
    s += __shfl_xor_sync(0xFFFFFFFFu, s, 1);
    return s;
}

__global__ __launch_bounds__(NTH, 1)
void lstm2_kernel(const float* __restrict__ x,
                  const float* __restrict__ W_ih0, const float* __restrict__ W_hh0,
                  const float* __restrict__ b_ih0, const float* __restrict__ b_hh0,
                  const float* __restrict__ W_ih1, const float* __restrict__ W_hh1,
                  const float* __restrict__ b_ih1, const float* __restrict__ b_hh1,
                  const float* __restrict__ fc_W, const float* __restrict__ fc_b,
                  float* __restrict__ out)
{
    extern __shared__ float sm[];
    float* sW0  = sm;                    // W_hh0  [4*KP][WS]
    float* sWi1 = sW0  + 4 * KP * WS;
    float* sWh1 = sWi1 + 4 * KP * WS;
    float* sX   = sWh1 + 4 * KP * WS;    // [BT][SXS]
    float* h1s  = sX   + BT * SXS;       // 2 bufs [BT][HS]
    float* h2s  = h1s  + 2 * HBUF;       // 2 bufs

    const int tid  = threadIdx.x;
    const int half = tid & 1;
    const int b    = (tid >> 1) & 3;
    const int k    = tid >> 3;           // 0..55 (50..55 dummy)
    const bool wr  = (k < HID) && (half == 0);
    const int bg   = blockIdx.x * BT;
    const int jb   = half * 7;           // ull2 chunk base for this half

    // ---- prologue: stage weights (zero-padded rows 50..55, cols 50..55) ----
    for (int i = tid; i < 4 * KP * WS; i += NTH) {
        int row = i / WS, c = i - row * WS;
        int g = row / KP, kr = row - g * KP;
        bool in = (kr < HID) && (c < HID);
        int src = (g * HID + kr) * HID + c;
        sW0 [i] = in ? W_hh0[src] : 0.0f;
        sWi1[i] = in ? W_ih1[src] : 0.0f;
        sWh1[i] = in ? W_hh1[src] : 0.0f;
    }
    for (int i = tid; i < BT * SEQL; i += NTH) {
        int bl = i >> 9;
        int t  = i & (SEQL - 1);
        sX[bl * SXS + t] = x[(size_t)(bg + bl) * SEQL + t];
    }
    for (int i = tid; i < 4 * HBUF; i += NTH) h1s[i] = 0.0f;  // h1s+h2s contiguous

    const int ksafe = (k < HID) ? k : 0;
    float wi0[4], bs0[4], bs1[4];
    #pragma unroll
    for (int g = 0; g < 4; g++) {
        int row = g * HID + ksafe;
        wi0[g] = W_ih0[row];
        bs0[g] = b_ih0[row] + b_hh0[row];
        bs1[g] = b_ih1[row] + b_hh1[row];
    }
    float c1[4] = {0, 0, 0, 0}, c2[4] = {0, 0, 0, 0};
    __syncthreads();

    const ulonglong2* w0k  = (const ulonglong2*)(sW0  + k * WS) + jb;
    const ulonglong2* wi1k = (const ulonglong2*)(sWi1 + k * WS) + jb;
    const ulonglong2* wh1k = (const ulonglong2*)(sWh1 + k * WS) + jb;

    // ---- peel u=0: L1 from x[0] only (h1[-1]=0); both halves track c1 ----
    {
        float* h1w = h1s;                // buf 0
        #pragma unroll
        for (int bb = 0; bb < 4; bb++) {
            float xt = sX[(b + 4 * bb) * SXS];
            float i1 = fsigm(fmaf(xt, wi0[0], bs0[0]));
            float g1 = ftanh(fmaf(xt, wi0[2], bs0[2]));
            float o1 = fsigm(fmaf(xt, wi0[3], bs0[3]));
            c1[bb] = i1 * g1;
            if (wr) h1w[(b + 4 * bb) * HS + k] = o1 * ftanh(c1[bb]);
        }
        __syncthreads();
    }

    // ---- main skewed loop: u = 1..511 -> L1(t=u) + L2(t=u-1) ----
    for (int u = 1; u < SEQL; u++) {
        const float* h1r = h1s + ((u + 1) & 1) * HBUF;   // h1[u-1]
        const float* h2r = h2s + (u & 1) * HBUF;         // h2[u-2]
        float* h1w = h1s + (u & 1) * HBUF;               // h1[u]
        float* h2w = h2s + ((u + 1) & 1) * HBUF;         // h2[u-1]

        unsigned long long a1[4][4], a2[4][4];
        #pragma unroll
        for (int g = 0; g < 4; g++)
            #pragma unroll
            for (int bb = 0; bb < 4; bb++) { a1[g][bb] = 0ULL; a2[g][bb] = 0ULL; }

        #pragma unroll
        for (int j = 0; j < 7; j++) {
            ulonglong2 h1v[4], h2v[4];
            #pragma unroll
            for (int bb = 0; bb < 4; bb++) {
                h1v[bb] = ((const ulonglong2*)(h1r + (b + 4 * bb) * HS))[jb + j];
                h2v[bb] = ((const ulonglong2*)(h2r + (b + 4 * bb) * HS))[jb + j];
            }
            #pragma unroll
            for (int g = 0; g < 4; g++) {
                ulonglong2 w;
                w = w0k[j + g * GS2];          // L1 recurrent
                #pragma unroll
                for (int bb = 0; bb < 4; bb++) {
                    fma2(a1[g][bb], w.x, h1v[bb].x);
                    fma2(a1[g][bb], w.y, h1v[bb].y);
                }
                w = wh1k[j + g * GS2];         // L2 recurrent
                #pragma unroll
                for (int bb = 0; bb < 4; bb++) {
                    fma2(a2[g][bb], w.x, h2v[bb].x);
                    fma2(a2[g][bb], w.y, h2v[bb].y);
                }
                w = wi1k[j + g * GS2];         // L2 input (h1[u-1])
                #pragma unroll
                for (int bb = 0; bb < 4; bb++) {
                    fma2(a2[g][bb], w.x, h1v[bb].x);
                    fma2(a2[g][bb], w.y, h1v[bb].y);
                }
            }
        }

        #pragma unroll
        for (int bb = 0; bb < 4; bb++) {
            // layer 1 at t=u
            float xt = sX[(b + 4 * bb) * SXS + u];
            float g0 = comb(a1[0][bb]) + fmaf(xt, wi0[0], bs0[0]);
            float g1 = comb(a1[1][bb]) + fmaf(xt, wi0[1], bs0[1]);
            float g2 = comb(a1[2][bb]) + fmaf(xt, wi0[2], bs0[2]);
            float g3 = comb(a1[3][bb]) + fmaf(xt, wi0[3], bs0[3]);
            float i1 = fsigm(g0), f1 = fsigm(g1), gg1 = ftanh(g2), o1 = fsigm(g3);
            c1[bb] = fmaf(f1, c1[bb], i1 * gg1);
            float h1n = o1 * ftanh(c1[bb]);
            // layer 2 at t=u-1
            float G0 = comb(a2[0][bb]) + bs1[0];
            float G1 = comb(a2[1][bb]) + bs1[1];
            float G2 = comb(a2[2][bb]) + bs1[2];
            float G3 = comb(a2[3][bb]) + bs1[3];
            float i2 = fsigm(G0), f2 = fsigm(G1), gg2 = ftanh(G2), o2 = fsigm(G3);
            c2[bb] = fmaf(f2, c2[bb], i2 * gg2);
            float h2n = o2 * ftanh(c2[bb]);
            if (wr) {
                h1w[(b + 4 * bb) * HS + k] = h1n;
                h2w[(b + 4 * bb) * HS + k] = h2n;
            }
        }
        __syncthreads();
    }

    // ---- tail: L2 at t=511 (u=512) ----
    {
        const float* h1r = h1s + HBUF;   // h1[511] (buf 1)
        const float* h2r = h2s;          // h2[510] (buf 0)
        unsigned long long a2[4][4];
        #pragma unroll
        for (int g = 0; g < 4; g++)
            #pragma unroll
            for (int bb = 0; bb < 4; bb++) a2[g][bb] = 0ULL;

        #pragma unroll
        for (int j = 0; j < 7; j++) {
            ulonglong2 h1v[4], h2v[4];
            #pragma unroll
            for (int bb = 0; bb < 4; bb++) {
                h1v[bb] = ((const ulonglong2*)(h1r + (b + 4 * bb) * HS))[jb + j];
                h2v[bb] = ((const ulonglong2*)(h2r + (b + 4 * bb) * HS))[jb + j];
            }
            #pragma unroll
            for (int g = 0; g < 4; g++) {
                ulonglong2 w;
                w = wh1k[j + g * GS2];
                #pragma unroll
                for (int bb = 0; bb < 4; bb++) {
                    fma2(a2[g][bb], w.x, h2v[bb].x);
                    fma2(a2[g][bb], w.y, h2v[bb].y);
                }
                w = wi1k[j + g * GS2];
                #pragma unroll
                for (int bb = 0; bb < 4; bb++) {
                    fma2(a2[g][bb], w.x, h1v[bb].x);
                    fma2(a2[g][bb], w.y, h1v[bb].y);
                }
            }
        }

        float* h2f = h2s + HBUF;         // scratch (dead buffer)
        #pragma unroll
        for (int bb = 0; bb < 4; bb++) {
            float G0 = comb(a2[0][bb]) + bs1[0];
            float G1 = comb(a2[1][bb]) + bs1[1];
            float G2 = comb(a2[2][bb]) + bs1[2];
            float G3 = comb(a2[3][bb]) + bs1[3];
            float i2 = fsigm(G0), f2 = fsigm(G1), gg2 = ftanh(G2), o2 = fsigm(G3);
            c2[bb] = fmaf(f2, c2[bb], i2 * gg2);
            if (wr) h2f[(b + 4 * bb) * HS + k] = o2 * ftanh(c2[bb]);
        }
        __syncthreads();

        // FC: out[b'] = h2[511] . fc_W + fc_b
        if (k == 0 && half == 0) {
            float fb = fc_b[0];
            #pragma unroll
            for (int bb = 0; bb < 4; bb++) {
                float acc = fb;
                const float* hrow = h2f + (b + 4 * bb) * HS;
                #pragma unroll
                for (int kk = 0; kk < HID; kk++)
                    acc = fmaf(hrow[kk], fc_W[kk], acc);
                out[bg + b + 4 * bb] = acc;
            }
        }
    }
}

extern "C" void kernel_launch(void* const* d_in, const int* in_sizes, int n_in,
                              void* d_out, int out_size)
{
    const float* x     = (const float*)d_in[0];
    const float* W_ih0 = (const float*)d_in[1];
    const float* W_hh0 = (const float*)d_in[2];
    const float* b_ih0 = (const float*)d_in[3];
    const float* b_hh0 = (const float*)d_in[4];
    const float* W_ih1 = (const float*)d_in[5];
    const float* W_hh1 = (const float*)d_in[6];
    const float* b_ih1 = (const float*)d_in[7];
    const float* b_hh1 = (const float*)d_in[8];
    const float* fc_W  = (const float*)d_in[9];
    const float* fc_b  = (const float*)d_in[10];
    float* out = (float*)d_out;

    const int smem_bytes = (3 * 4 * KP * WS + BT * SXS + 4 * HBUF) * (int)sizeof(float);
    cudaFuncSetAttribute(lstm2_kernel, cudaFuncAttributeMaxDynamicSharedMemorySize, smem_bytes);
    lstm2_kernel<<<NBATCH / BT, NTH, smem_bytes>>>(
        x, W_ih0, W_hh0, b_ih0, b_hh0,
        W_ih1, W_hh1, b_ih1, b_hh1, fc_W, fc_b, out);
}

// round 7
// speedup vs baseline: 1.6998x; 1.6998x over previous
#include <cuda_runtime.h>

// 2-layer LSTM (B=2048, T=512, I=1, H=50) + FC(50->1), tensor-core version.
// 128 persistent CTAs x 16 batch, 320 threads (10 warps).
// Per step: two tf32 GEMMs via mma.sync.m16n8k8:
//   G1[400x16] = A1[400x56] . B1[56x16],  B1 = [h1; x; 1; 0]
//   G2[240x16] = A2[240x56] . B2[56x16],  B2 = [h2; 0]
// A held in REGISTERS (weight-stationary, 112 regs/thread). h stored hi+lo
// tf32 pair -> 2 chained mmas recover ~fp32 h precision. Biases and the
// x-term are folded into A1 cols 50/51. Gate math on 1600 (k,b,layer) quads,
// 5 per thread, c-state in registers. Layer-skewed: step u does L1(t=u),
// L2(t=u-1). Two barriers/step.

#define HID   50
#define BT    16
#define SEQL  512
#define NBATCH 2048
#define NTH   320
#define BS    24            // B-buffer row stride (floats): banks perfect
#define GS    24            // G-buffer row stride
#define BROWS 56
#define BBUF  (BROWS * BS)  // 1344
#define SXS   513

// SMEM float offsets
#define OFF_SX   0
#define OFF_B1H  (OFF_SX + BT * SXS)        // 8208
#define OFF_B1L  (OFF_B1H + 2 * BBUF)
#define OFF_B2H  (OFF_B1L + 2 * BBUF)
#define OFF_B2L  (OFF_B2H + 2 * BBUF)
#define OFF_G1   (OFF_B2L + 2 * BBUF)       // 400 rows
#define OFF_G2   (OFF_G1 + 400 * GS)        // 240 rows
#define SMEM_FLOATS (OFF_G2 + 240 * GS)     // 34320 floats = 137.3 KB

__device__ __forceinline__ unsigned rna(float f) {
    unsigned r; asm("cvt.rna.tf32.f32 %0, %1;" : "=r"(r) : "f"(f)); return r;
}
__device__ __forceinline__ float ftanh(float v) {
    float y; asm("tanh.approx.f32 %0, %1;" : "=f"(y) : "f"(v)); return y;
}
__device__ __forceinline__ float fsigm(float v) {
    return fmaf(0.5f, ftanh(0.5f * v), 0.5f);
}
__device__ __forceinline__ void mma8(float* d, const unsigned* a,
                                     unsigned b0, unsigned b1) {
    asm("mma.sync.aligned.m16n8k8.row.col.f32.tf32.tf32.f32 "
        "{%0,%1,%2,%3}, {%4,%5,%6,%7}, {%8,%9}, {%0,%1,%2,%3};"
        : "+f"(d[0]), "+f"(d[1]), "+f"(d[2]), "+f"(d[3])
        : "r"(a[0]), "r"(a[1]), "r"(a[2]), "r"(a[3]), "r"(b0), "r"(b1));
}

__global__ __launch_bounds__(NTH, 1)
void lstm2_kernel(const float* __restrict__ x,
                  const float* __restrict__ W_ih0, const float* __restrict__ W_hh0,
                  const float* __restrict__ b_ih0, const float* __restrict__ b_hh0,
                  const float* __restrict__ W_ih1, const float* __restrict__ W_hh1,
                  const float* __restrict__ b_ih1, const float* __restrict__ b_hh1,
                  const float* __restrict__ fc_W, const float* __restrict__ fc_b,
                  float* __restrict__ out)
{
    extern __shared__ float smf[];
    float* sX  = smf + OFF_SX;
    float* B1H = smf + OFF_B1H;
    float* B1L = smf + OFF_B1L;
    float* B2H = smf + OFF_B2H;
    float* B2L = smf + OFF_B2L;
    float* G1s = smf + OFF_G1;
    float* G2s = smf + OFF_G2;

    const int tid  = threadIdx.x;
    const int w    = tid >> 5;
    const int lane = tid & 31;
    const int g    = lane >> 2;       // groupID (fragment row base)
    const int tq   = lane & 3;        // threadID_in_group
    const int bg   = blockIdx.x * BT;

    // ---- prologue: x tile + zero B buffers ----
    for (int i = tid; i < BT * SEQL; i += NTH) {
        int bl = i >> 9, t = i & (SEQL - 1);
        sX[bl * SXS + t] = x[(size_t)(bg + bl) * SEQL + t];
    }
    for (int i = tid; i < 8 * BBUF; i += NTH) B1H[i] = 0.0f;  // all 8 B bufs contiguous
    __syncthreads();
    if (tid < BT) {
        // bias row 51 = 1.0 in both B1H bufs (never rewritten)
        B1H[0 * BBUF + 51 * BS + tid] = 1.0f;
        B1H[1 * BBUF + 51 * BS + tid] = 1.0f;
        // x[0] hi/lo into buf 0 row 50
        float xv = sX[tid * SXS];
        float xh = __uint_as_float(rna(xv));
        B1H[0 * BBUF + 50 * BS + tid] = xh;
        B1L[0 * BBUF + 50 * BS + tid] = __uint_as_float(rna(xv - xh));
    }

    // ---- load A fragments into registers (weight-stationary) ----
    // Mtile m = w + 10*tl; m<25 -> A1 rows 16m; else A2 rows 16(m-25).
    unsigned Ar[4][7][4];
    #pragma unroll
    for (int tl = 0; tl < 4; tl++) {
        const int m = w + 10 * tl;
        const bool isg1 = (m < 25);
        const int rb = isg1 ? 16 * m : 16 * (m - 25);
        #pragma unroll
        for (int kt = 0; kt < 7; kt++) {
            #pragma unroll
            for (int rr = 0; rr < 2; rr++) {       // row g / g+8
                #pragma unroll
                for (int cc = 0; cc < 2; cc++) {   // col tq / tq+4
                    int r = rb + g + 8 * rr;
                    int c = kt * 8 + tq + 4 * cc;
                    float v = 0.0f;
                    if (isg1) {
                        if (r < 200) {
                            if (c < HID)       v = W_hh0[r * HID + c];
                            else if (c == 50)  v = W_ih0[r];
                            else if (c == 51)  v = b_ih0[r] + b_hh0[r];
                        } else {
                            int r2 = r - 200;
                            if (c < HID)       v = W_ih1[r2 * HID + c];
                            else if (c == 51)  v = b_ih1[r2] + b_hh1[r2];
                        }
                    } else {
                        if (r < 200 && c < HID) v = W_hh1[r * HID + c];
                    }
                    Ar[tl][kt][rr + 2 * cc] = rna(v);
                }
            }
        }
    }

    float cst[5] = {0, 0, 0, 0, 0};
    __syncthreads();

    // ---- main loop: u = 0..512.  L1(t=u) for u<512, L2(t=u-1) for u>0 ----
    for (int u = 0; u <= SEQL; u++) {
        const int p = u & 1, q = p ^ 1;
        const float* b1h = B1H + p * BBUF;
        const float* b1l = B1L + p * BBUF;
        const float* b2h = B2H + p * BBUF;
        const float* b2l = B2L + p * BBUF;

        float d[4][2][4];
        #pragma unroll
        for (int tl = 0; tl < 4; tl++)
            #pragma unroll
            for (int n = 0; n < 2; n++)
                #pragma unroll
                for (int r = 0; r < 4; r++) d[tl][n][r] = 0.0f;

        #pragma unroll
        for (int kt = 0; kt < 7; kt++) {
            const int k0 = (kt * 8 + tq) * BS;
            const int k1 = (kt * 8 + tq + 4) * BS;
            unsigned f1h[2][2], f1l[2][2], f2h[2][2], f2l[2][2];
            #pragma unroll
            for (int n = 0; n < 2; n++) {
                const int cn = g + 8 * n;
                f1h[n][0] = __float_as_uint(b1h[k0 + cn]);
                f1h[n][1] = __float_as_uint(b1h[k1 + cn]);
                f1l[n][0] = __float_as_uint(b1l[k0 + cn]);
                f1l[n][1] = __float_as_uint(b1l[k1 + cn]);
                f2h[n][0] = __float_as_uint(b2h[k0 + cn]);
                f2h[n][1] = __float_as_uint(b2h[k1 + cn]);
                f2l[n][0] = __float_as_uint(b2l[k0 + cn]);
                f2l[n][1] = __float_as_uint(b2l[k1 + cn]);
            }
            // tiles 0,1: always G1 (B1); tile 3: always G2 (B2); tile 2: w<5 ? G1 : G2
            #pragma unroll
            for (int n = 0; n < 2; n++) {
                mma8(d[0][n], Ar[0][kt], f1h[n][0], f1h[n][1]);
                mma8(d[0][n], Ar[0][kt], f1l[n][0], f1l[n][1]);
                mma8(d[1][n], Ar[1][kt], f1h[n][0], f1h[n][1]);
                mma8(d[1][n], Ar[1][kt], f1l[n][0], f1l[n][1]);
                mma8(d[3][n], Ar[3][kt], f2h[n][0], f2h[n][1]);
                mma8(d[3][n], Ar[3][kt], f2l[n][0], f2l[n][1]);
            }
            if (w < 5) {
                #pragma unroll
                for (int n = 0; n < 2; n++) {
                    mma8(d[2][n], Ar[2][kt], f1h[n][0], f1h[n][1]);
                    mma8(d[2][n], Ar[2][kt], f1l[n][0], f1l[n][1]);
                }
            } else {
                #pragma unroll
                for (int n = 0; n < 2; n++) {
                    mma8(d[2][n], Ar[2][kt], f2h[n][0], f2h[n][1]);
                    mma8(d[2][n], Ar[2][kt], f2l[n][0], f2l[n][1]);
                }
            }
        }

        // ---- D -> Gbuf ----
        #pragma unroll
        for (int tl = 0; tl < 4; tl++) {
            const int m = w + 10 * tl;
            float* Gb = (m < 25) ? (G1s + (16 * m) * GS)
                                 : (G2s + (16 * (m - 25)) * GS);
            #pragma unroll
            for (int n = 0; n < 2; n++) {
                const int cb = 2 * tq + 8 * n;
                *(float2*)(Gb + g * GS + cb)       = make_float2(d[tl][n][0], d[tl][n][1]);
                *(float2*)(Gb + (g + 8) * GS + cb) = make_float2(d[tl][n][2], d[tl][n][3]);
            }
        }
        __syncthreads();

        // ---- gate phase: 5 quads/thread ----
        float* w1h = B1H + q * BBUF;
        float* w1l = B1L + q * BBUF;
        float* w2h = B2H + q * BBUF;
        float* w2l = B2L + q * BBUF;
        #pragma unroll
        for (int j = 0; j < 5; j++) {
            const int qid = j * NTH + tid;
            if (qid < 800) {           // layer 1, t = u
                if (u < SEQL) {
                    const int kk = qid >> 4, bb = qid & 15;
                    float p0 = G1s[(0 * HID + kk) * GS + bb];
                    float p1 = G1s[(1 * HID + kk) * GS + bb];
                    float p2 = G1s[(2 * HID + kk) * GS + bb];
                    float p3 = G1s[(3 * HID + kk) * GS + bb];
                    float i1 = fsigm(p0), ff = fsigm(p1);
                    float gg = ftanh(p2), o1 = fsigm(p3);
                    cst[j] = fmaf(ff, cst[j], i1 * gg);
                    float h = o1 * ftanh(cst[j]);
                    float hh = __uint_as_float(rna(h));
                    w1h[kk * BS + bb] = hh;
                    w1l[kk * BS + bb] = __uint_as_float(rna(h - hh));
                    if (kk == 0 && u + 1 < SEQL) {
                        float xv = sX[bb * SXS + (u + 1)];
                        float xh = __uint_as_float(rna(xv));
                        w1h[50 * BS + bb] = xh;
                        w1l[50 * BS + bb] = __uint_as_float(rna(xv - xh));
                    }
                }
            } else {                   // layer 2, t = u-1
                if (u > 0) {
                    const int idx = qid - 800;
                    const int kk = idx >> 4, bb = idx & 15;
                    float p0 = G1s[(200 + 0 * HID + kk) * GS + bb] + G2s[(0 * HID + kk) * GS + bb];
                    float p1 = G1s[(200 + 1 * HID + kk) * GS + bb] + G2s[(1 * HID + kk) * GS + bb];
                    float p2 = G1s[(200 + 2 * HID + kk) * GS + bb] + G2s[(2 * HID + kk) * GS + bb];
                    float p3 = G1s[(200 + 3 * HID + kk) * GS + bb] + G2s[(3 * HID + kk) * GS + bb];
                    float i2 = fsigm(p0), ff = fsigm(p1);
                    float gg = ftanh(p2), o2 = fsigm(p3);
                    cst[j] = fmaf(ff, cst[j], i2 * gg);
                    float h = o2 * ftanh(cst[j]);
                    float hh = __uint_as_float(rna(h));
                    w2h[kk * BS + bb] = hh;
                    w2l[kk * BS + bb] = __uint_as_float(rna(h - hh));
                }
            }
        }
        __syncthreads();
    }

    // ---- FC epilogue: h2[511] lives in B2 buf 1 (hi+lo) ----
    if (tid < BT) {
        const float* hh = B2H + 1 * BBUF;
        const float* hl = B2L + 1 * BBUF;
        float acc = fc_b[0];
        #pragma unroll
        for (int kk = 0; kk < HID; kk++)
            acc = fmaf(hh[kk * BS + tid] + hl[kk * BS + tid], fc_W[kk], acc);
        out[bg + tid] = acc;
    }
}

extern "C" void kernel_launch(void* const* d_in, const int* in_sizes, int n_in,
                              void* d_out, int out_size)
{
    const float* x     = (const float*)d_in[0];
    const float* W_ih0 = (const float*)d_in[1];
    const float* W_hh0 = (const float*)d_in[2];
    const float* b_ih0 = (const float*)d_in[3];
    const float* b_hh0 = (const float*)d_in[4];
    const float* W_ih1 = (const float*)d_in[5];
    const float* W_hh1 = (const float*)d_in[6];
    const float* b_ih1 = (const float*)d_in[7];
    const float* b_hh1 = (const float*)d_in[8];
    const float* fc_W  = (const float*)d_in[9];
    const float* fc_b  = (const float*)d_in[10];
    float* out = (float*)d_out;

    const int smem_bytes = SMEM_FLOATS * (int)sizeof(float);
    cudaFuncSetAttribute(lstm2_kernel, cudaFuncAttributeMaxDynamicSharedMemorySize, smem_bytes);
    lstm2_kernel<<<NBATCH / BT, NTH, smem_bytes>>>(
        x, W_ih0, W_hh0, b_ih0, b_hh0,
        W_ih1, W_hh1, b_ih1, b_hh1, fc_W, fc_b, out);
}

// round 8
// speedup vs baseline: 2.0199x; 1.1884x over previous
#include <cuda_runtime.h>

// 2-layer LSTM (B=2048, T=512, I=1, H=50) + FC(50->1), tf32 tensor-core.
// 128 persistent CTAs x 16 batch, 448 threads (14 warps).
// Per step (layer-skewed): G1[432x16] = A1 . [h1;x;1;0] (rows 0..399 real),
// G2[240x16] = W_hh1 . [h2;0]. A in registers (weight-stationary, 84 regs).
// 42 M-tiles, 3/warp: warps 0-8 pure-G1, warps 9-13 pure-G2 (each loads
// only its own B fragments). h carried as tf32 hi+lo -> 2 chained mmas.
// Gate math: 1600 quads, 4 iters/thread, c-state in registers.

#define HID   50
#define BT    16
#define SEQL  512
#define NBATCH 2048
#define NTH   448
#define BS    24            // B-buffer row stride (floats)
#define GS    24            // G-buffer row stride
#define BROWS 56
#define BBUF  (BROWS * BS)  // 1344
#define SXS   513

#define OFF_SX   0
#define OFF_B1H  (OFF_SX + BT * SXS)        // 8208
#define OFF_B1L  (OFF_B1H + 2 * BBUF)
#define OFF_B2H  (OFF_B1L + 2 * BBUF)
#define OFF_B2L  (OFF_B2H + 2 * BBUF)
#define OFF_G1   (OFF_B2L + 2 * BBUF)       // 432 rows (400 real)
#define OFF_G2   (OFF_G1 + 432 * GS)        // 240 rows
#define SMEM_FLOATS (OFF_G2 + 240 * GS)     // 35088 floats = 140.4 KB

__device__ __forceinline__ unsigned rna(float f) {
    unsigned r; asm("cvt.rna.tf32.f32 %0, %1;" : "=r"(r) : "f"(f)); return r;
}
__device__ __forceinline__ float ftanh(float v) {
    float y; asm("tanh.approx.f32 %0, %1;" : "=f"(y) : "f"(v)); return y;
}
__device__ __forceinline__ float fsigm(float v) {
    return fmaf(0.5f, ftanh(0.5f * v), 0.5f);
}
__device__ __forceinline__ void mma8(float* d, const unsigned* a,
                                     unsigned b0, unsigned b1) {
    asm("mma.sync.aligned.m16n8k8.row.col.f32.tf32.tf32.f32 "
        "{%0,%1,%2,%3}, {%4,%5,%6,%7}, {%8,%9}, {%0,%1,%2,%3};"
        : "+f"(d[0]), "+f"(d[1]), "+f"(d[2]), "+f"(d[3])
        : "r"(a[0]), "r"(a[1]), "r"(a[2]), "r"(a[3]), "r"(b0), "r"(b1));
}

__global__ __launch_bounds__(NTH, 1)
void lstm2_kernel(const float* __restrict__ x,
                  const float* __restrict__ W_ih0, const float* __restrict__ W_hh0,
                  const float* __restrict__ b_ih0, const float* __restrict__ b_hh0,
                  const float* __restrict__ W_ih1, const float* __restrict__ W_hh1,
                  const float* __restrict__ b_ih1, const float* __restrict__ b_hh1,
                  const float* __restrict__ fc_W, const float* __restrict__ fc_b,
                  float* __restrict__ out)
{
    extern __shared__ float smf[];
    float* sX  = smf + OFF_SX;
    float* B1H = smf + OFF_B1H;
    float* B1L = smf + OFF_B1L;
    float* B2H = smf + OFF_B2H;
    float* B2L = smf + OFF_B2L;
    float* G1s = smf + OFF_G1;
    float* G2s = smf + OFF_G2;

    const int tid  = threadIdx.x;
    const int w    = tid >> 5;
    const int lane = tid & 31;
    const int g    = lane >> 2;       // fragment row base
    const int tq   = lane & 3;        // thread-in-group
    const int bg   = blockIdx.x * BT;
    const bool isG1w = (w < 9);       // warps 0-8: G1 (27 tiles); 9-13: G2 (15)

    // ---- prologue: x tile + zero B bufs ----
    for (int i = tid; i < BT * SEQL; i += NTH) {
        int bl = i >> 9, t = i & (SEQL - 1);
        sX[bl * SXS + t] = x[(size_t)(bg + bl) * SEQL + t];
    }
    for (int i = tid; i < 8 * BBUF; i += NTH) B1H[i] = 0.0f;
    __syncthreads();
    if (tid < BT) {
        B1H[0 * BBUF + 51 * BS + tid] = 1.0f;      // bias rows (both bufs)
        B1H[1 * BBUF + 51 * BS + tid] = 1.0f;
        float xv = sX[tid * SXS];
        float xh = __uint_as_float(rna(xv));
        B1H[0 * BBUF + 50 * BS + tid] = xh;
        B1L[0 * BBUF + 50 * BS + tid] = __uint_as_float(rna(xv - xh));
    }

    // ---- weight-stationary A fragments: 3 tiles/warp ----
    unsigned Ar[3][7][4];
    {
        const int tbase = isG1w ? 3 * w : 3 * (w - 9);
        #pragma unroll
        for (int tl = 0; tl < 3; tl++) {
            const int rb = 16 * (tbase + tl);
            #pragma unroll
            for (int kt = 0; kt < 7; kt++) {
                #pragma unroll
                for (int rr = 0; rr < 2; rr++) {
                    #pragma unroll
                    for (int cc = 0; cc < 2; cc++) {
                        int r = rb + g + 8 * rr;
                        int c = kt * 8 + tq + 4 * cc;
                        float v = 0.0f;
                        if (isG1w) {
                            if (r < 200) {
                                if (c < HID)       v = W_hh0[r * HID + c];
                                else if (c == 50)  v = W_ih0[r];
                                else if (c == 51)  v = b_ih0[r] + b_hh0[r];
                            } else if (r < 400) {
                                int r2 = r - 200;
                                if (c < HID)       v = W_ih1[r2 * HID + c];
                                else if (c == 51)  v = b_ih1[r2] + b_hh1[r2];
                            }
                        } else {
                            if (c < HID) v = W_hh1[r * HID + c];  // r < 240 always
                        }
                        Ar[tl][kt][rr + 2 * cc] = rna(v);
                    }
                }
            }
        }
    }

    float cst[4] = {0, 0, 0, 0};
    __syncthreads();

    // ---- main loop: u=0..512. L1(t=u) for u<512, L2(t=u-1) for u>0 ----
    for (int u = 0; u <= SEQL; u++) {
        const int p = u & 1, q = p ^ 1;
        const float* bh = (isG1w ? B1H : B2H) + p * BBUF;
        const float* bl = (isG1w ? B1L : B2L) + p * BBUF;

        float d[3][2][4];
        #pragma unroll
        for (int tl = 0; tl < 3; tl++)
            #pragma unroll
            for (int n = 0; n < 2; n++)
                #pragma unroll
                for (int r = 0; r < 4; r++) d[tl][n][r] = 0.0f;

        #pragma unroll
        for (int kt = 0; kt < 7; kt++) {
            const int k0 = (kt * 8 + tq) * BS;
            const int k1 = (kt * 8 + tq + 4) * BS;
            unsigned fh[2][2], fl[2][2];
            #pragma unroll
            for (int n = 0; n < 2; n++) {
                const int cn = g + 8 * n;
                fh[n][0] = __float_as_uint(bh[k0 + cn]);
                fh[n][1] = __float_as_uint(bh[k1 + cn]);
                fl[n][0] = __float_as_uint(bl[k0 + cn]);
                fl[n][1] = __float_as_uint(bl[k1 + cn]);
            }
            #pragma unroll
            for (int tl = 0; tl < 3; tl++) {
                #pragma unroll
                for (int n = 0; n < 2; n++) {
                    mma8(d[tl][n], Ar[tl][kt], fh[n][0], fh[n][1]);
                    mma8(d[tl][n], Ar[tl][kt], fl[n][0], fl[n][1]);
                }
            }
        }

        // ---- D -> G buffers ----
        {
            const int tbase = isG1w ? 3 * w : 3 * (w - 9);
            float* Gb = (isG1w ? G1s : G2s) + (16 * tbase) * GS;
            #pragma unroll
            for (int tl = 0; tl < 3; tl++) {
                float* Gt = Gb + (16 * tl) * GS;
                #pragma unroll
                for (int n = 0; n < 2; n++) {
                    const int cb = 2 * tq + 8 * n;
                    *(float2*)(Gt + g * GS + cb)       = make_float2(d[tl][n][0], d[tl][n][1]);
                    *(float2*)(Gt + (g + 8) * GS + cb) = make_float2(d[tl][n][2], d[tl][n][3]);
                }
            }
        }
        __syncthreads();

        // ---- gate phase: 1600 quads, 4 per thread ----
        float* w1h = B1H + q * BBUF;
        float* w1l = B1L + q * BBUF;
        float* w2h = B2H + q * BBUF;
        float* w2l = B2L + q * BBUF;
        #pragma unroll
        for (int j = 0; j < 4; j++) {
            const int qid = j * NTH + tid;
            if (qid < 800) {              // layer 1, t = u
                if (u < SEQL) {
                    const int kk = qid >> 4, bb = qid & 15;
                    float p0 = G1s[(0 * HID + kk) * GS + bb];
                    float p1 = G1s[(1 * HID + kk) * GS + bb];
                    float p2 = G1s[(2 * HID + kk) * GS + bb];
                    float p3 = G1s[(3 * HID + kk) * GS + bb];
                    float i1 = fsigm(p0), ff = fsigm(p1);
                    float gg = ftanh(p2), o1 = fsigm(p3);
                    cst[j] = fmaf(ff, cst[j], i1 * gg);
                    float h = o1 * ftanh(cst[j]);
                    float hh = __uint_as_float(rna(h));
                    w1h[kk * BS + bb] = hh;
                    w1l[kk * BS + bb] = __uint_as_float(rna(h - hh));
                    if (kk == 0 && u + 1 < SEQL) {
                        float xv = sX[bb * SXS + (u + 1)];
                        float xh = __uint_as_float(rna(xv));
                        w1h[50 * BS + bb] = xh;
                        w1l[50 * BS + bb] = __uint_as_float(rna(xv - xh));
                    }
                }
            } else if (qid < 1600) {      // layer 2, t = u-1
                if (u > 0) {
                    const int idx = qid - 800;
                    const int kk = idx >> 4, bb = idx & 15;
                    float p0 = G1s[(200 + 0 * HID + kk) * GS + bb] + G2s[(0 * HID + kk) * GS + bb];
                    float p1 = G1s[(200 + 1 * HID + kk) * GS + bb] + G2s[(1 * HID + kk) * GS + bb];
                    float p2 = G1s[(200 + 2 * HID + kk) * GS + bb] + G2s[(2 * HID + kk) * GS + bb];
                    float p3 = G1s[(200 + 3 * HID + kk) * GS + bb] + G2s[(3 * HID + kk) * GS + bb];
                    float i2 = fsigm(p0), ff = fsigm(p1);
                    float gg = ftanh(p2), o2 = fsigm(p3);
                    cst[j] = fmaf(ff, cst[j], i2 * gg);
                    float h = o2 * ftanh(cst[j]);
                    float hh = __uint_as_float(rna(h));
                    w2h[kk * BS + bb] = hh;
                    w2l[kk * BS + bb] = __uint_as_float(rna(h - hh));
                }
            }
        }
        __syncthreads();
    }

    // ---- FC epilogue: h2[511] in B2 buf 1 (hi+lo) ----
    if (tid < BT) {
        const float* hh = B2H + 1 * BBUF;
        const float* hl = B2L + 1 * BBUF;
        float acc = fc_b[0];
        #pragma unroll
        for (int kk = 0; kk < HID; kk++)
            acc = fmaf(hh[kk * BS + tid] + hl[kk * BS + tid], fc_W[kk], acc);
        out[bg + tid] = acc;
    }
}

extern "C" void kernel_launch(void* const* d_in, const int* in_sizes, int n_in,
                              void* d_out, int out_size)
{
    const float* x     = (const float*)d_in[0];
    const float* W_ih0 = (const float*)d_in[1];
    const float* W_hh0 = (const float*)d_in[2];
    const float* b_ih0 = (const float*)d_in[3];
    const float* b_hh0 = (const float*)d_in[4];
    const float* W_ih1 = (const float*)d_in[5];
    const float* W_hh1 = (const float*)d_in[6];
    const float* b_ih1 = (const float*)d_in[7];
    const float* b_hh1 = (const float*)d_in[8];
    const float* fc_W  = (const float*)d_in[9];
    const float* fc_b  = (const float*)d_in[10];
    float* out = (float*)d_out;

    const int smem_bytes = SMEM_FLOATS * (int)sizeof(float);
    cudaFuncSetAttribute(lstm2_kernel, cudaFuncAttributeMaxDynamicSharedMemorySize, smem_bytes);
    lstm2_kernel<<<NBATCH / BT, NTH, smem_bytes>>>(
        x, W_ih0, W_hh0, b_ih0, b_hh0,
        W_ih1, W_hh1, b_ih1, b_hh1, fc_W, fc_b, out);
}

// round 9
// speedup vs baseline: 2.1424x; 1.0607x over previous
#include <cuda_runtime.h>

// 2-layer LSTM (B=2048, T=512, I=1, H=50) + FC(50->1), tf32 tensor-core v3.
// 128 persistent CTAs x 16 batch, 416 threads (13 warps).
// GATE-INTERLEAVED rows: A row 4k+j = gate j of hidden k  =>  all 4 gates of
// a hidden unit live in ONE 16-row M-tile => gate math is WARP-LOCAL
// (private scratch + syncwarp), only ONE __syncthreads per step.
// Unified B[112x16] = [h1; x; 1; pad; h2; pad]:
//   L1: A1[208x56]  (W_hh0 | wi0 | bias1), kt 0..6
//   L2: A2[208x112] (W_ih1 | 0 | bias2 | 0 | W_hh1), kt 0..13
// B fragments shared between the two gemms. h carried tf32 hi+lo.
// Warp w owns L1 tile w and L2 tile w (k = 4w..4w+3). c-state in registers.

#define HID   50
#define BT    16
#define SEQL  512
#define NBATCH 2048
#define NW    13
#define NTH   (NW * 32)      // 416
#define BS    24             // B row stride (floats)
#define BROWS 120            // 112 + pad
#define BBUF  (BROWS * BS)   // 2880
#define SXS   513
#define SCRS  20             // transposed scratch col stride
#define SCRT  (16 * SCRS)    // 320 floats per tile

#define OFF_SX  0
#define OFF_BH  (OFF_SX + BT * SXS)      // 8208
#define OFF_BL  (OFF_BH + 2 * BBUF)
#define OFF_SCR (OFF_BL + 2 * BBUF)
#define SMEM_FLOATS (OFF_SCR + NW * 2 * SCRT)   // 28048 fl = 112.2 KB

__device__ __forceinline__ unsigned rna(float f) {
    unsigned r; asm("cvt.rna.tf32.f32 %0, %1;" : "=r"(r) : "f"(f)); return r;
}
__device__ __forceinline__ float ftanh(float v) {
    float y; asm("tanh.approx.f32 %0, %1;" : "=f"(y) : "f"(v)); return y;
}
__device__ __forceinline__ float fsigm(float v) {
    return fmaf(0.5f, ftanh(0.5f * v), 0.5f);
}
__device__ __forceinline__ void mma8(float* d, const unsigned* a,
                                     unsigned b0, unsigned b1) {
    asm("mma.sync.aligned.m16n8k8.row.col.f32.tf32.tf32.f32 "
        "{%0,%1,%2,%3}, {%4,%5,%6,%7}, {%8,%9}, {%0,%1,%2,%3};"
        : "+f"(d[0]), "+f"(d[1]), "+f"(d[2]), "+f"(d[3])
        : "r"(a[0]), "r"(a[1]), "r"(a[2]), "r"(a[3]), "r"(b0), "r"(b1));
}

__global__ __launch_bounds__(NTH, 1)
void lstm2_kernel(const float* __restrict__ x,
                  const float* __restrict__ W_ih0, const float* __restrict__ W_hh0,
                  const float* __restrict__ b_ih0, const float* __restrict__ b_hh0,
                  const float* __restrict__ W_ih1, const float* __restrict__ W_hh1,
                  const float* __restrict__ b_ih1, const float* __restrict__ b_hh1,
                  const float* __restrict__ fc_W, const float* __restrict__ fc_b,
                  float* __restrict__ out)
{
    extern __shared__ float smf[];
    float* sX  = smf + OFF_SX;
    float* BH  = smf + OFF_BH;     // [2][BROWS*BS] tf32-hi
    float* BL  = smf + OFF_BL;     // [2][BROWS*BS] tf32-lo
    float* SCR = smf + OFF_SCR;    // [NW][2][16*SCRS] transposed D scratch

    const int tid  = threadIdx.x;
    const int w    = tid >> 5;
    const int lane = tid & 31;
    const int g    = lane >> 2;
    const int tq   = lane & 3;
    const int bg   = blockIdx.x * BT;

    // ---- prologue: x tile, zero B bufs, constants ----
    for (int i = tid; i < BT * SEQL; i += NTH) {
        int bl = i >> 9, t = i & (SEQL - 1);
        sX[bl * SXS + t] = x[(size_t)(bg + bl) * SEQL + t];
    }
    for (int i = tid; i < 4 * BBUF; i += NTH) BH[i] = 0.0f;  // BH+BL contiguous
    __syncthreads();
    if (tid < BT) {
        BH[0 * BBUF + 51 * BS + tid] = 1.0f;   // bias row, both bufs
        BH[1 * BBUF + 51 * BS + tid] = 1.0f;
        float xv = sX[tid * SXS];
        float xh = __uint_as_float(rna(xv));
        BH[0 * BBUF + 50 * BS + tid] = xh;
        BL[0 * BBUF + 50 * BS + tid] = __uint_as_float(rna(xv - xh));
    }

    // ---- weight-stationary fragments (gate-interleaved rows) ----
    // A row r: k = r>>2, gate j = r&3 (k >= 50 -> zero pad)
    unsigned A1r[7][4], A2r[14][4];
    #pragma unroll
    for (int kt = 0; kt < 14; kt++) {
        #pragma unroll
        for (int rr = 0; rr < 2; rr++) {
            #pragma unroll
            for (int cc = 0; cc < 2; cc++) {
                const int r = 16 * w + g + 8 * rr;
                const int c = kt * 8 + tq + 4 * cc;
                const int kk = r >> 2, j = r & 3;
                const int wrow = j * HID + kk;       // row in original W layout
                float v1 = 0.0f, v2 = 0.0f;
                if (kk < HID) {
                    if (kt < 7) {                    // A1 cols 0..55
                        if (c < HID)      v1 = W_hh0[wrow * HID + c];
                        else if (c == 50) v1 = W_ih0[wrow];
                        else if (c == 51) v1 = b_ih0[wrow] + b_hh0[wrow];
                    }
                    if (c < HID)            v2 = W_ih1[wrow * HID + c];
                    else if (c == 51)       v2 = b_ih1[wrow] + b_hh1[wrow];
                    else if (c >= 56 && c < 106) v2 = W_hh1[wrow * HID + (c - 56)];
                }
                if (kt < 7) A1r[kt][rr + 2 * cc] = rna(v1);
                A2r[kt][rr + 2 * cc] = rna(v2);
            }
        }
    }

    // gate-phase mapping: thread handles (k_loc, b) pairs, k_loc = kh, kh+2
    const int b  = lane & 15;
    const int kh = lane >> 4;
    float c1[2] = {0, 0}, c2[2] = {0, 0};
    float* scr1 = SCR + (w * 2) * SCRT;
    float* scr2 = scr1 + SCRT;
    __syncthreads();

    // ---- main loop: u = 0..512. L1 gates at t=u (u<512), L2 at t=u-1 (u>0) ----
    for (int u = 0; u <= SEQL; u++) {
        const int p = u & 1, q = p ^ 1;
        const float* bh = BH + p * BBUF;
        const float* blo = BL + p * BBUF;

        float d1[2][4], d2[2][4];
        #pragma unroll
        for (int n = 0; n < 2; n++)
            #pragma unroll
            for (int r = 0; r < 4; r++) { d1[n][r] = 0.0f; d2[n][r] = 0.0f; }

        #pragma unroll
        for (int kt = 0; kt < 14; kt++) {
            const int k0 = (kt * 8 + tq) * BS;
            const int k1 = (kt * 8 + tq + 4) * BS;
            unsigned fh[2][2], fl[2][2];
            #pragma unroll
            for (int n = 0; n < 2; n++) {
                const int cn = g + 8 * n;
                fh[n][0] = __float_as_uint(bh [k0 + cn]);
                fh[n][1] = __float_as_uint(bh [k1 + cn]);
                fl[n][0] = __float_as_uint(blo[k0 + cn]);
                fl[n][1] = __float_as_uint(blo[k1 + cn]);
            }
            #pragma unroll
            for (int n = 0; n < 2; n++) {
                mma8(d2[n], A2r[kt], fh[n][0], fh[n][1]);
                mma8(d2[n], A2r[kt], fl[n][0], fl[n][1]);
            }
            if (kt < 7) {
                #pragma unroll
                for (int n = 0; n < 2; n++) {
                    mma8(d1[n], A1r[kt], fh[n][0], fh[n][1]);
                    mma8(d1[n], A1r[kt], fl[n][0], fl[n][1]);
                }
            }
        }

        // ---- D -> warp-private transposed scratch: scr[col][row] ----
        #pragma unroll
        for (int n = 0; n < 2; n++) {
            const int c0 = (2 * tq + 8 * n) * SCRS;
            scr1[c0 + g]            = d1[n][0];
            scr1[c0 + SCRS + g]     = d1[n][1];
            scr1[c0 + g + 8]        = d1[n][2];
            scr1[c0 + SCRS + g + 8] = d1[n][3];
            scr2[c0 + g]            = d2[n][0];
            scr2[c0 + SCRS + g]     = d2[n][1];
            scr2[c0 + g + 8]        = d2[n][2];
            scr2[c0 + SCRS + g + 8] = d2[n][3];
        }
        __syncwarp();

        // ---- warp-local gate math: quads (k_loc, b), k = 4w + k_loc ----
        float* wh = BH + q * BBUF;
        float* wl = BL + q * BBUF;
        #pragma unroll
        for (int qi = 0; qi < 2; qi++) {
            const int kloc = kh + 2 * qi;
            const int kk = 4 * w + kloc;
            // layer 1, t = u
            if (u < SEQL) {
                float4 G = *(const float4*)(scr1 + b * SCRS + 4 * kloc);
                float i1 = fsigm(G.x), f1 = fsigm(G.y);
                float gg = ftanh(G.z), o1 = fsigm(G.w);
                c1[qi] = fmaf(f1, c1[qi], i1 * gg);
                float h = o1 * ftanh(c1[qi]);
                float hhv = __uint_as_float(rna(h));
                if (kk < HID) {
                    wh[kk * BS + b] = hhv;
                    wl[kk * BS + b] = __uint_as_float(rna(h - hhv));
                }
            }
            // layer 2, t = u-1
            if (u > 0) {
                float4 G = *(const float4*)(scr2 + b * SCRS + 4 * kloc);
                float i2 = fsigm(G.x), f2 = fsigm(G.y);
                float gg = ftanh(G.z), o2 = fsigm(G.w);
                c2[qi] = fmaf(f2, c2[qi], i2 * gg);
                float h = o2 * ftanh(c2[qi]);
                float hhv = __uint_as_float(rna(h));
                if (kk < HID) {
                    wh[(56 + kk) * BS + b] = hhv;
                    wl[(56 + kk) * BS + b] = __uint_as_float(rna(h - hhv));
                }
            }
        }
        // x[u+1] into row 50 of next buffer (warp 0, lanes 0-15)
        if (w == 0 && lane < 16 && u + 1 < SEQL) {
            float xv = sX[lane * SXS + (u + 1)];
            float xh = __uint_as_float(rna(xv));
            wh[50 * BS + lane] = xh;
            wl[50 * BS + lane] = __uint_as_float(rna(xv - xh));
        }
        __syncthreads();
    }

    // ---- FC epilogue: h2[511] in buf q of final step = buf 1, rows 56..105 ----
    if (tid < BT) {
        const float* hh = BH + 1 * BBUF;
        const float* hl = BL + 1 * BBUF;
        float acc = fc_b[0];
        #pragma unroll
        for (int kk = 0; kk < HID; kk++)
            acc = fmaf(hh[(56 + kk) * BS + tid] + hl[(56 + kk) * BS + tid],
                       fc_W[kk], acc);
        out[bg + tid] = acc;
    }
}

extern "C" void kernel_launch(void* const* d_in, const int* in_sizes, int n_in,
                              void* d_out, int out_size)
{
    const float* x     = (const float*)d_in[0];
    const float* W_ih0 = (const float*)d_in[1];
    const float* W_hh0 = (const float*)d_in[2];
    const float* b_ih0 = (const float*)d_in[3];
    const float* b_hh0 = (const float*)d_in[4];
    const float* W_ih1 = (const float*)d_in[5];
    const float* W_hh1 = (const float*)d_in[6];
    const float* b_ih1 = (const float*)d_in[7];
    const float* b_hh1 = (const float*)d_in[8];
    const float* fc_W  = (const float*)d_in[9];
    const float* fc_b  = (const float*)d_in[10];
    float* out = (float*)d_out;

    const int smem_bytes = SMEM_FLOATS * (int)sizeof(float);
    cudaFuncSetAttribute(lstm2_kernel, cudaFuncAttributeMaxDynamicSharedMemorySize, smem_bytes);
    lstm2_kernel<<<NBATCH / BT, NTH, smem_bytes>>>(
        x, W_ih0, W_hh0, b_ih0, b_hh0,
        W_ih1, W_hh1, b_ih1, b_hh1, fc_W, fc_b, out);
}

// round 10
// speedup vs baseline: 3.3938x; 1.5841x over previous
#include <cuda_runtime.h>

// 2-layer LSTM (B=2048, T=512, I=1, H=50) + FC(50->1), tf32 tensor-core v4.
// 128 persistent CTAs x 16 batch, 416 threads (13 warps).
// Single-pass tf32 h (no hi/lo compensation): halves tensor work AND
// SMEM crossbar bytes vs v3. Gate-interleaved A rows (row 4k+j = gate j of
// hidden k) => warp-local gate math, ONE __syncthreads per step.
// Unified B[112x16] = [h1; x; 1; pad; h2; pad]:
//   L1: A1[208x56]  (W_hh0 | wi0 | bias1), kt 0..6
//   L2: A2[208x112] (W_ih1 | 0 | bias2 | 0 | W_hh1), kt 0..13
// Warp w owns L1 tile w and L2 tile w (k = 4w..4w+3). c-state in registers.

#define HID   50
#define BT    16
#define SEQL  512
#define NBATCH 2048
#define NW    13
#define NTH   (NW * 32)      // 416
#define BS    24             // B row stride (floats)
#define BROWS 120            // 112 + pad
#define BBUF  (BROWS * BS)   // 2880
#define SXS   513
#define SCRS  20             // transposed scratch col stride
#define SCRT  (16 * SCRS)    // 320 floats per tile

#define OFF_SX  0
#define OFF_BH  (OFF_SX + BT * SXS)      // 8208
#define OFF_SCR (OFF_BH + 2 * BBUF)
#define SMEM_FLOATS (OFF_SCR + NW * 2 * SCRT)   // 22288 fl = 89.2 KB

__device__ __forceinline__ unsigned rna(float f) {
    unsigned r; asm("cvt.rna.tf32.f32 %0, %1;" : "=r"(r) : "f"(f)); return r;
}
__device__ __forceinline__ float ftanh(float v) {
    float y; asm("tanh.approx.f32 %0, %1;" : "=f"(y) : "f"(v)); return y;
}
__device__ __forceinline__ float fsigm(float v) {
    return fmaf(0.5f, ftanh(0.5f * v), 0.5f);
}
__device__ __forceinline__ void mma8(float* d, const unsigned* a,
                                     unsigned b0, unsigned b1) {
    asm("mma.sync.aligned.m16n8k8.row.col.f32.tf32.tf32.f32 "
        "{%0,%1,%2,%3}, {%4,%5,%6,%7}, {%8,%9}, {%0,%1,%2,%3};"
        : "+f"(d[0]), "+f"(d[1]), "+f"(d[2]), "+f"(d[3])
        : "r"(a[0]), "r"(a[1]), "r"(a[2]), "r"(a[3]), "r"(b0), "r"(b1));
}

__global__ __launch_bounds__(NTH, 1)
void lstm2_kernel(const float* __restrict__ x,
                  const float* __restrict__ W_ih0, const float* __restrict__ W_hh0,
                  const float* __restrict__ b_ih0, const float* __restrict__ b_hh0,
                  const float* __restrict__ W_ih1, const float* __restrict__ W_hh1,
                  const float* __restrict__ b_ih1, const float* __restrict__ b_hh1,
                  const float* __restrict__ fc_W, const float* __restrict__ fc_b,
                  float* __restrict__ out)
{
    extern __shared__ float smf[];
    float* sX  = smf + OFF_SX;
    float* BH  = smf + OFF_BH;     // [2][BROWS*BS] tf32 values
    float* SCR = smf + OFF_SCR;    // [NW][2][16*SCRS] transposed D scratch

    const int tid  = threadIdx.x;
    const int w    = tid >> 5;
    const int lane = tid & 31;
    const int g    = lane >> 2;
    const int tq   = lane & 3;
    const int bg   = blockIdx.x * BT;

    // ---- prologue: x tile, zero B bufs, constants ----
    for (int i = tid; i < BT * SEQL; i += NTH) {
        int bl = i >> 9, t = i & (SEQL - 1);
        sX[bl * SXS + t] = x[(size_t)(bg + bl) * SEQL + t];
    }
    for (int i = tid; i < 2 * BBUF; i += NTH) BH[i] = 0.0f;
    __syncthreads();
    if (tid < BT) {
        BH[0 * BBUF + 51 * BS + tid] = 1.0f;   // bias row, both bufs
        BH[1 * BBUF + 51 * BS + tid] = 1.0f;
        BH[0 * BBUF + 50 * BS + tid] = __uint_as_float(rna(sX[tid * SXS]));
    }

    // ---- weight-stationary fragments (gate-interleaved rows) ----
    // A row r: k = r>>2, gate j = r&3 (k >= 50 -> zero pad)
    unsigned A1r[7][4], A2r[14][4];
    #pragma unroll
    for (int kt = 0; kt < 14; kt++) {
        #pragma unroll
        for (int rr = 0; rr < 2; rr++) {
            #pragma unroll
            for (int cc = 0; cc < 2; cc++) {
                const int r = 16 * w + g + 8 * rr;
                const int c = kt * 8 + tq + 4 * cc;
                const int kk = r >> 2, j = r & 3;
                const int wrow = j * HID + kk;       // row in original W layout
                float v1 = 0.0f, v2 = 0.0f;
                if (kk < HID) {
                    if (kt < 7) {                    // A1 cols 0..55
                        if (c < HID)      v1 = W_hh0[wrow * HID + c];
                        else if (c == 50) v1 = W_ih0[wrow];
                        else if (c == 51) v1 = b_ih0[wrow] + b_hh0[wrow];
                    }
                    if (c < HID)            v2 = W_ih1[wrow * HID + c];
                    else if (c == 51)       v2 = b_ih1[wrow] + b_hh1[wrow];
                    else if (c >= 56 && c < 106) v2 = W_hh1[wrow * HID + (c - 56)];
                }
                if (kt < 7) A1r[kt][rr + 2 * cc] = rna(v1);
                A2r[kt][rr + 2 * cc] = rna(v2);
            }
        }
    }

    // gate-phase mapping: thread handles (k_loc, b) pairs, k_loc = kh, kh+2
    const int b  = lane & 15;
    const int kh = lane >> 4;
    float c1[2] = {0, 0}, c2[2] = {0, 0};
    float* scr1 = SCR + (w * 2) * SCRT;
    float* scr2 = scr1 + SCRT;
    __syncthreads();

    // ---- main loop: u = 0..512. L1 gates at t=u (u<512), L2 at t=u-1 (u>0) ----
    for (int u = 0; u <= SEQL; u++) {
        const int p = u & 1, q = p ^ 1;
        const float* bh = BH + p * BBUF;

        float d1[2][4], d2[2][4];
        #pragma unroll
        for (int n = 0; n < 2; n++)
            #pragma unroll
            for (int r = 0; r < 4; r++) { d1[n][r] = 0.0f; d2[n][r] = 0.0f; }

        #pragma unroll
        for (int kt = 0; kt < 14; kt++) {
            const int k0 = (kt * 8 + tq) * BS;
            const int k1 = (kt * 8 + tq + 4) * BS;
            unsigned fh[2][2];
            #pragma unroll
            for (int n = 0; n < 2; n++) {
                const int cn = g + 8 * n;
                fh[n][0] = __float_as_uint(bh[k0 + cn]);
                fh[n][1] = __float_as_uint(bh[k1 + cn]);
            }
            #pragma unroll
            for (int n = 0; n < 2; n++)
                mma8(d2[n], A2r[kt], fh[n][0], fh[n][1]);
            if (kt < 7) {
                #pragma unroll
                for (int n = 0; n < 2; n++)
                    mma8(d1[n], A1r[kt], fh[n][0], fh[n][1]);
            }
        }

        // ---- D -> warp-private transposed scratch: scr[col][row] ----
        #pragma unroll
        for (int n = 0; n < 2; n++) {
            const int c0 = (2 * tq + 8 * n) * SCRS;
            scr1[c0 + g]            = d1[n][0];
            scr1[c0 + SCRS + g]     = d1[n][1];
            scr1[c0 + g + 8]        = d1[n][2];
            scr1[c0 + SCRS + g + 8] = d1[n][3];
            scr2[c0 + g]            = d2[n][0];
            scr2[c0 + SCRS + g]     = d2[n][1];
            scr2[c0 + g + 8]        = d2[n][2];
            scr2[c0 + SCRS + g + 8] = d2[n][3];
        }
        __syncwarp();

        // ---- warp-local gate math: quads (k_loc, b), k = 4w + k_loc ----
        float* wh = BH + q * BBUF;
        #pragma unroll
        for (int qi = 0; qi < 2; qi++) {
            const int kloc = kh + 2 * qi;
            const int kk = 4 * w + kloc;
            // layer 1, t = u
            if (u < SEQL) {
                float4 G = *(const float4*)(scr1 + b * SCRS + 4 * kloc);
                float i1 = fsigm(G.x), f1 = fsigm(G.y);
                float gg = ftanh(G.z), o1 = fsigm(G.w);
                c1[qi] = fmaf(f1, c1[qi], i1 * gg);
                float h = o1 * ftanh(c1[qi]);
                if (kk < HID)
                    wh[kk * BS + b] = __uint_as_float(rna(h));
            }
            // layer 2, t = u-1
            if (u > 0) {
                float4 G = *(const float4*)(scr2 + b * SCRS + 4 * kloc);
                float i2 = fsigm(G.x), f2 = fsigm(G.y);
                float gg = ftanh(G.z), o2 = fsigm(G.w);
                c2[qi] = fmaf(f2, c2[qi], i2 * gg);
                float h = o2 * ftanh(c2[qi]);
                if (kk < HID)
                    wh[(56 + kk) * BS + b] = __uint_as_float(rna(h));
            }
        }
        // x[u+1] into row 50 of next buffer (warp 0, lanes 0-15)
        if (w == 0 && lane < 16 && u + 1 < SEQL)
            wh[50 * BS + lane] = __uint_as_float(rna(sX[lane * SXS + (u + 1)]));
        __syncthreads();
    }

    // ---- FC epilogue: h2[511] in buf 1, rows 56..105 ----
    if (tid < BT) {
        const float* hh = BH + 1 * BBUF;
        float acc = fc_b[0];
        #pragma unroll
        for (int kk = 0; kk < HID; kk++)
            acc = fmaf(hh[(56 + kk) * BS + tid], fc_W[kk], acc);
        out[bg + tid] = acc;
    }
}

extern "C" void kernel_launch(void* const* d_in, const int* in_sizes, int n_in,
                              void* d_out, int out_size)
{
    const float* x     = (const float*)d_in[0];
    const float* W_ih0 = (const float*)d_in[1];
    const float* W_hh0 = (const float*)d_in[2];
    const float* b_ih0 = (const float*)d_in[3];
    const float* b_hh0 = (const float*)d_in[4];
    const float* W_ih1 = (const float*)d_in[5];
    const float* W_hh1 = (const float*)d_in[6];
    const float* b_ih1 = (const float*)d_in[7];
    const float* b_hh1 = (const float*)d_in[8];
    const float* fc_W  = (const float*)d_in[9];
    const float* fc_b  = (const float*)d_in[10];
    float* out = (float*)d_out;

    const int smem_bytes = SMEM_FLOATS * (int)sizeof(float);
    cudaFuncSetAttribute(lstm2_kernel, cudaFuncAttributeMaxDynamicSharedMemorySize, smem_bytes);
    lstm2_kernel<<<NBATCH / BT, NTH, smem_bytes>>>(
        x, W_ih0, W_hh0, b_ih0, b_hh0,
        W_ih1, W_hh1, b_ih1, b_hh1, fc_W, fc_b, out);
}

// round 11
// speedup vs baseline: 4.6105x; 1.3585x over previous
#include <cuda_runtime.h>
#include <cuda_fp16.h>

// 2-layer LSTM (B=2048, T=512, I=1, H=50) + FC(50->1), fp16 tensor-core v5.
// 128 persistent CTAs x 16 batch, 416 threads (13 warps).
// mma.m16n8k16.f32.f16.f16.f32: fp16 mantissa == tf32 mantissa (10 bits), all
// values are O(1) so fp16 range is free => same accuracy as tf32, half the
// bytes and half the mma count. Gate-interleaved A rows (row 4k+j = gate j of
// hidden k) => warp-local gate math, ONE __syncthreads per step.
// Unified B[112x16] stored TRANSPOSED [batch][k] in f16 (stride 136 halves,
// conflict-free): k = [h1(0..49); x(50); 1(51); pad; h2(56..105); pad].
//   L1: A1[208x64]  (W_hh0 | wi0 | bias1 | 0), kt 0..3
//   L2: A2[208x112] (W_ih1 | 0 | bias2 | 0 | W_hh1 | 0), kt 0..6
// B fragments shared between the gemms. Warp w owns L1 tile w + L2 tile w.

#define HID   50
#define BT    16
#define SEQL  512
#define NBATCH 2048
#define NW    13
#define NTH   (NW * 32)      // 416
#define BSTR  136            // B row stride in halves ([batch][k])
#define BBUFH (BT * BSTR)    // 2176 halves per buffer
#define SXS   513
#define SCRS  20             // transposed scratch col stride
#define SCRT  (16 * SCRS)    // 320 floats per tile

#define OFF_SX  0
#define OFF_BH  (OFF_SX + BT * SXS)          // 8208 floats
#define OFF_SCR (OFF_BH + 2 * BBUFH / 2)     // 2 bufs * 2176 halves = 2176 fl
#define SMEM_FLOATS (OFF_SCR + NW * 2 * SCRT)   // 18704 fl = 74.8 KB

__device__ __forceinline__ float ftanh(float v) {
    float y; asm("tanh.approx.f32 %0, %1;" : "=f"(y) : "f"(v)); return y;
}
__device__ __forceinline__ float fsigm(float v) {
    return fmaf(0.5f, ftanh(0.5f * v), 0.5f);
}
__device__ __forceinline__ unsigned packh2(float lo, float hi) {
    // bits[15:0] = h(lo), bits[31:16] = h(hi)
    unsigned r;
    asm("cvt.rn.f16x2.f32 %0, %1, %2;" : "=r"(r) : "f"(hi), "f"(lo));
    return r;
}
__device__ __forceinline__ void mma16(float* d, const unsigned* a,
                                      unsigned b0, unsigned b1) {
    asm("mma.sync.aligned.m16n8k16.row.col.f32.f16.f16.f32 "
        "{%0,%1,%2,%3}, {%4,%5,%6,%7}, {%8,%9}, {%0,%1,%2,%3};"
        : "+f"(d[0]), "+f"(d[1]), "+f"(d[2]), "+f"(d[3])
        : "r"(a[0]), "r"(a[1]), "r"(a[2]), "r"(a[3]), "r"(b0), "r"(b1));
}

__global__ __launch_bounds__(NTH, 1)
void lstm2_kernel(const float* __restrict__ x,
                  const float* __restrict__ W_ih0, const float* __restrict__ W_hh0,
                  const float* __restrict__ b_ih0, const float* __restrict__ b_hh0,
                  const float* __restrict__ W_ih1, const float* __restrict__ W_hh1,
                  const float* __restrict__ b_ih1, const float* __restrict__ b_hh1,
                  const float* __restrict__ fc_W, const float* __restrict__ fc_b,
                  float* __restrict__ out)
{
    extern __shared__ float smf[];
    float*  sX  = smf + OFF_SX;
    __half* BH  = (__half*)(smf + OFF_BH);   // [2][BT][BSTR] halves
    float*  SCR = smf + OFF_SCR;             // [NW][2][16*SCRS]

    const int tid  = threadIdx.x;
    const int w    = tid >> 5;
    const int lane = tid & 31;
    const int g    = lane >> 2;
    const int tq   = lane & 3;
    const int bg   = blockIdx.x * BT;

    // ---- prologue: x tile, zero B bufs ----
    for (int i = tid; i < BT * SEQL; i += NTH) {
        int bl = i >> 9, t = i & (SEQL - 1);
        sX[bl * SXS + t] = x[(size_t)(bg + bl) * SEQL + t];
    }
    for (int i = tid; i < 2 * BBUFH / 2; i += NTH)   // zero as floats
        ((float*)BH)[i] = 0.0f;
    __syncthreads();
    if (tid < BT) {
        BH[0 * BBUFH + tid * BSTR + 51] = __float2half(1.0f);  // bias col, both bufs
        BH[1 * BBUFH + tid * BSTR + 51] = __float2half(1.0f);
        BH[0 * BBUFH + tid * BSTR + 50] = __float2half(sX[tid * SXS]);  // x[0]
    }

    // ---- weight-stationary fp16 A fragments (gate-interleaved rows) ----
    // A row r: k = r>>2, gate j = r&3 (k >= 50 -> zero). wrow = j*50+k.
    unsigned A1r[4][4], A2r[7][4];
    #pragma unroll
    for (int kt = 0; kt < 7; kt++) {
        #pragma unroll
        for (int rr = 0; rr < 2; rr++) {
            #pragma unroll
            for (int cc = 0; cc < 2; cc++) {
                const int r  = 16 * w + g + 8 * rr;
                const int c0 = kt * 16 + 2 * tq + 8 * cc;   // even col
                const int kk = r >> 2, j = r & 3;
                const int wrow = j * HID + kk;
                float v1[2] = {0.0f, 0.0f}, v2[2] = {0.0f, 0.0f};
                #pragma unroll
                for (int e = 0; e < 2; e++) {
                    const int c = c0 + e;
                    if (kk < HID) {
                        if (kt < 4) {                       // A1, cols 0..63
                            if (c < HID)      v1[e] = W_hh0[wrow * HID + c];
                            else if (c == 50) v1[e] = W_ih0[wrow];
                            else if (c == 51) v1[e] = b_ih0[wrow] + b_hh0[wrow];
                        }
                        if (c < HID)            v2[e] = W_ih1[wrow * HID + c];
                        else if (c == 51)       v2[e] = b_ih1[wrow] + b_hh1[wrow];
                        else if (c >= 56 && c < 106) v2[e] = W_hh1[wrow * HID + (c - 56)];
                    }
                }
                if (kt < 4) A1r[kt][rr + 2 * cc] = packh2(v1[0], v1[1]);
                A2r[kt][rr + 2 * cc] = packh2(v2[0], v2[1]);
            }
        }
    }

    // gate-phase mapping: thread handles (k_loc, b) quads, k_loc = kh, kh+2
    const int b  = lane & 15;
    const int kh = lane >> 4;
    float c1[2] = {0, 0}, c2[2] = {0, 0};
    float* scr1 = SCR + (w * 2) * SCRT;
    float* scr2 = scr1 + SCRT;
    __syncthreads();

    // ---- main loop: u = 0..512. L1 gates at t=u (u<512), L2 at t=u-1 (u>0) ----
    for (int u = 0; u <= SEQL; u++) {
        const int p = u & 1, q = p ^ 1;
        const __half* bh = BH + p * BBUFH;

        float d1[2][4], d2[2][4];
        #pragma unroll
        for (int n = 0; n < 2; n++)
            #pragma unroll
            for (int r = 0; r < 4; r++) { d1[n][r] = 0.0f; d2[n][r] = 0.0f; }

        #pragma unroll
        for (int kt = 0; kt < 7; kt++) {
            unsigned fb[2][2];
            #pragma unroll
            for (int n = 0; n < 2; n++) {
                const __half* rowp = bh + (g + 8 * n) * BSTR + kt * 16 + 2 * tq;
                fb[n][0] = *(const unsigned*)(rowp);        // k = 16kt+2tq, +1
                fb[n][1] = *(const unsigned*)(rowp + 8);    // k = +8, +9
            }
            #pragma unroll
            for (int n = 0; n < 2; n++)
                mma16(d2[n], A2r[kt], fb[n][0], fb[n][1]);
            if (kt < 4) {
                #pragma unroll
                for (int n = 0; n < 2; n++)
                    mma16(d1[n], A1r[kt], fb[n][0], fb[n][1]);
            }
        }

        // ---- D -> warp-private transposed scratch: scr[col][row] ----
        #pragma unroll
        for (int n = 0; n < 2; n++) {
            const int c0 = (2 * tq + 8 * n) * SCRS;
            scr1[c0 + g]            = d1[n][0];
            scr1[c0 + SCRS + g]     = d1[n][1];
            scr1[c0 + g + 8]        = d1[n][2];
            scr1[c0 + SCRS + g + 8] = d1[n][3];
            scr2[c0 + g]            = d2[n][0];
            scr2[c0 + SCRS + g]     = d2[n][1];
            scr2[c0 + g + 8]        = d2[n][2];
            scr2[c0 + SCRS + g + 8] = d2[n][3];
        }
        __syncwarp();

        // ---- warp-local gate math: quads (k_loc, b), k = 4w + k_loc ----
        __half* wh = BH + q * BBUFH;
        #pragma unroll
        for (int qi = 0; qi < 2; qi++) {
            const int kloc = kh + 2 * qi;
            const int kk = 4 * w + kloc;
            // layer 1, t = u
            if (u < SEQL) {
                float4 G = *(const float4*)(scr1 + b * SCRS + 4 * kloc);
                float i1 = fsigm(G.x), f1 = fsigm(G.y);
                float gg = ftanh(G.z), o1 = fsigm(G.w);
                c1[qi] = fmaf(f1, c1[qi], i1 * gg);
                float h = o1 * ftanh(c1[qi]);
                if (kk < HID)
                    wh[b * BSTR + kk] = __float2half(h);
            }
            // layer 2, t = u-1
            if (u > 0) {
                float4 G = *(const float4*)(scr2 + b * SCRS + 4 * kloc);
                float i2 = fsigm(G.x), f2 = fsigm(G.y);
                float gg = ftanh(G.z), o2 = fsigm(G.w);
                c2[qi] = fmaf(f2, c2[qi], i2 * gg);
                float h = o2 * ftanh(c2[qi]);
                if (kk < HID)
                    wh[b * BSTR + 56 + kk] = __float2half(h);
            }
        }
        // x[u+1] into col 50 of next buffer (warp 0, lanes 0-15)
        if (w == 0 && lane < 16 && u + 1 < SEQL)
            wh[lane * BSTR + 50] = __float2half(sX[lane * SXS + (u + 1)]);
        __syncthreads();
    }

    // ---- FC epilogue: h2[511] in buf 1, cols 56..105 ----
    if (tid < BT) {
        const __half* hh = BH + 1 * BBUFH + tid * BSTR;
        float acc = fc_b[0];
        #pragma unroll
        for (int kk = 0; kk < HID; kk++)
            acc = fmaf(__half2float(hh[56 + kk]), fc_W[kk], acc);
        out[bg + tid] = acc;
    }
}

extern "C" void kernel_launch(void* const* d_in, const int* in_sizes, int n_in,
                              void* d_out, int out_size)
{
    const float* x     = (const float*)d_in[0];
    const float* W_ih0 = (const float*)d_in[1];
    const float* W_hh0 = (const float*)d_in[2];
    const float* b_ih0 = (const float*)d_in[3];
    const float* b_hh0 = (const float*)d_in[4];
    const float* W_ih1 = (const float*)d_in[5];
    const float* W_hh1 = (const float*)d_in[6];
    const float* b_ih1 = (const float*)d_in[7];
    const float* b_hh1 = (const float*)d_in[8];
    const float* fc_W  = (const float*)d_in[9];
    const float* fc_b  = (const float*)d_in[10];
    float* out = (float*)d_out;

    const int smem_bytes = SMEM_FLOATS * (int)sizeof(float);
    cudaFuncSetAttribute(lstm2_kernel, cudaFuncAttributeMaxDynamicSharedMemorySize, smem_bytes);
    lstm2_kernel<<<NBATCH / BT, NTH, smem_bytes>>>(
        x, W_ih0, W_hh0, b_ih0, b_hh0,
        W_ih1, W_hh1, b_ih1, b_hh1, fc_W, fc_b, out);
}

// round 12
// speedup vs baseline: 6.3927x; 1.3866x over previous
#include <cuda_runtime.h>
#include <cuda_fp16.h>

// 2-layer LSTM (B=2048, T=512, I=1, H=50) + FC(50->1), fp16 tensor-core v6.
// 128 persistent CTAs x 16 batch, 832 threads = TWO groups of 13 warps.
// Each group owns 8 batches with its OWN B buffers and OWN named barrier
// (bar.sync 1 / bar.sync 2, 416 threads) -> the groups free-run half a
// phase apart, overlapping one group's gate/MUFU phase with the other's
// mma/LDS phase. Same totals per SM as v5, ~2x overlap.
// Per group, warp wl owns M-tile wl (gate-interleaved rows 4k+j):
//   L1: A1[208x64]  (W_hh0 | wi0 | bias1 | 0),            kt 0..3
//   L2: A2[208x112] (W_ih1 | 0 | bias2 | 0 | W_hh1 | 0),  kt 0..6
// B[batch][k] f16 (stride 136): k = [h1; x(50); 1(51); pad; h2(56..105)].

#define HID   50
#define BT    16
#define SEQL  512
#define NBATCH 2048
#define NWG   13             // warps per group
#define NTH   832
#define BSTR  136            // B row stride in halves
#define BBUFH (8 * BSTR)     // 1088 halves per buffer (8 batches)
#define SXS   513
#define SCRS  20
#define SCRT  (16 * SCRS)    // 320 floats per tile

#define OFF_SX  0
#define OFF_BH  (BT * SXS)                    // 8208 floats
#define OFF_SCR (OFF_BH + 4 * BBUFH / 2)      // 2 grp * 2 bufs * 1088 h = 2176 fl
#define SMEM_FLOATS (OFF_SCR + 2 * NWG * 2 * SCRT)   // 27024 fl = 108.1 KB

__device__ __forceinline__ float ftanh(float v) {
    float y; asm("tanh.approx.f32 %0, %1;" : "=f"(y) : "f"(v)); return y;
}
__device__ __forceinline__ float fsigm(float v) {
    return fmaf(0.5f, ftanh(0.5f * v), 0.5f);
}
__device__ __forceinline__ unsigned packh2(float lo, float hi) {
    unsigned r;
    asm("cvt.rn.f16x2.f32 %0, %1, %2;" : "=r"(r) : "f"(hi), "f"(lo));
    return r;
}
__device__ __forceinline__ void mma16(float* d, const unsigned* a,
                                      unsigned b0, unsigned b1) {
    asm("mma.sync.aligned.m16n8k16.row.col.f32.f16.f16.f32 "
        "{%0,%1,%2,%3}, {%4,%5,%6,%7}, {%8,%9}, {%0,%1,%2,%3};"
        : "+f"(d[0]), "+f"(d[1]), "+f"(d[2]), "+f"(d[3])
        : "r"(a[0]), "r"(a[1]), "r"(a[2]), "r"(a[3]), "r"(b0), "r"(b1));
}

__global__ __launch_bounds__(NTH, 1)
void lstm2_kernel(const float* __restrict__ x,
                  const float* __restrict__ W_ih0, const float* __restrict__ W_hh0,
                  const float* __restrict__ b_ih0, const float* __restrict__ b_hh0,
                  const float* __restrict__ W_ih1, const float* __restrict__ W_hh1,
                  const float* __restrict__ b_ih1, const float* __restrict__ b_hh1,
                  const float* __restrict__ fc_W, const float* __restrict__ fc_b,
                  float* __restrict__ out)
{
    extern __shared__ float smf[];
    float*  sX  = smf + OFF_SX;
    __half* BH  = (__half*)(smf + OFF_BH);   // [2 grp][2 buf][8][BSTR]
    float*  SCR = smf + OFF_SCR;             // [26 warps][2][SCRT]

    const int tid  = threadIdx.x;
    const int w    = tid >> 5;
    const int lane = tid & 31;
    const int g    = lane >> 2;
    const int tq   = lane & 3;
    const int wg   = (w >= NWG) ? 1 : 0;     // batch group 0/1
    const int wl   = w - NWG * wg;           // warp-in-group 0..12
    const int bg   = blockIdx.x * BT;

    // ---- prologue: x tile, zero B bufs ----
    for (int i = tid; i < BT * SEQL; i += NTH) {
        int bl = i >> 9, t = i & (SEQL - 1);
        sX[bl * SXS + t] = x[(size_t)(bg + bl) * SEQL + t];
    }
    for (int i = tid; i < 4 * BBUFH / 2; i += NTH)
        ((float*)BH)[i] = 0.0f;
    __syncthreads();
    if (tid < 16) {
        const int g2 = tid >> 3, bq2 = tid & 7;
        __half* base = BH + g2 * 2 * BBUFH;
        base[bq2 * BSTR + 51]         = __float2half(1.0f);  // bias, buf 0
        base[BBUFH + bq2 * BSTR + 51] = __float2half(1.0f);  // bias, buf 1
        base[bq2 * BSTR + 50] = __float2half(sX[(8 * g2 + bq2) * SXS]);  // x[0]
    }

    // ---- weight-stationary fp16 A fragments (gate-interleaved rows) ----
    unsigned A1r[4][4], A2r[7][4];
    #pragma unroll
    for (int kt = 0; kt < 7; kt++) {
        #pragma unroll
        for (int rr = 0; rr < 2; rr++) {
            #pragma unroll
            for (int cc = 0; cc < 2; cc++) {
                const int r  = 16 * wl + g + 8 * rr;
                const int c0 = kt * 16 + 2 * tq + 8 * cc;
                const int kk = r >> 2, j = r & 3;
                const int wrow = j * HID + kk;
                float v1[2] = {0.0f, 0.0f}, v2[2] = {0.0f, 0.0f};
                #pragma unroll
                for (int e = 0; e < 2; e++) {
                    const int c = c0 + e;
                    if (kk < HID) {
                        if (kt < 4) {
                            if (c < HID)      v1[e] = W_hh0[wrow * HID + c];
                            else if (c == 50) v1[e] = W_ih0[wrow];
                            else if (c == 51) v1[e] = b_ih0[wrow] + b_hh0[wrow];
                        }
                        if (c < HID)            v2[e] = W_ih1[wrow * HID + c];
                        else if (c == 51)       v2[e] = b_ih1[wrow] + b_hh1[wrow];
                        else if (c >= 56 && c < 106) v2[e] = W_hh1[wrow * HID + (c - 56)];
                    }
                }
                if (kt < 4) A1r[kt][rr + 2 * cc] = packh2(v1[0], v1[1]);
                A2r[kt][rr + 2 * cc] = packh2(v2[0], v2[1]);
            }
        }
    }

    __half* gBH  = BH + wg * 2 * BBUFH;
    float*  scr1 = SCR + (w * 2) * SCRT;
    float*  scr2 = scr1 + SCRT;
    const int bq   = lane & 7;        // gate batch (group-local)
    const int kloc = lane >> 3;       // gate hidden-in-tile 0..3
    const int kk   = 4 * wl + kloc;
    float c1 = 0.0f, c2 = 0.0f;
    __syncthreads();

    // ---- main loop (per group, independent barriers) ----
    for (int u = 0; u <= SEQL; u++) {
        const int p = u & 1, q = p ^ 1;
        const __half* bh = gBH + p * BBUFH;

        float d1[4] = {0, 0, 0, 0}, d2[4] = {0, 0, 0, 0};
        #pragma unroll
        for (int kt = 0; kt < 7; kt++) {
            const __half* rowp = bh + g * BSTR + kt * 16 + 2 * tq;
            const unsigned b0 = *(const unsigned*)(rowp);
            const unsigned b1 = *(const unsigned*)(rowp + 8);
            mma16(d2, A2r[kt], b0, b1);
            if (kt < 4) mma16(d1, A1r[kt], b0, b1);
        }

        // D -> warp-private transposed scratch scr[col][row]
        scr1[(2 * tq)     * SCRS + g]     = d1[0];
        scr1[(2 * tq + 1) * SCRS + g]     = d1[1];
        scr1[(2 * tq)     * SCRS + g + 8] = d1[2];
        scr1[(2 * tq + 1) * SCRS + g + 8] = d1[3];
        scr2[(2 * tq)     * SCRS + g]     = d2[0];
        scr2[(2 * tq + 1) * SCRS + g]     = d2[1];
        scr2[(2 * tq)     * SCRS + g + 8] = d2[2];
        scr2[(2 * tq + 1) * SCRS + g + 8] = d2[3];
        __syncwarp();

        // warp-local gate math: one quad per layer per thread
        __half* wh = gBH + q * BBUFH;
        if (u < SEQL) {                       // layer 1, t = u
            float4 G = *(const float4*)(scr1 + bq * SCRS + 4 * kloc);
            float i1 = fsigm(G.x), f1 = fsigm(G.y);
            float gg = ftanh(G.z), o1 = fsigm(G.w);
            c1 = fmaf(f1, c1, i1 * gg);
            float h = o1 * ftanh(c1);
            if (kk < HID) wh[bq * BSTR + kk] = __float2half(h);
        }
        if (u > 0) {                          // layer 2, t = u-1
            float4 G = *(const float4*)(scr2 + bq * SCRS + 4 * kloc);
            float i2 = fsigm(G.x), f2 = fsigm(G.y);
            float gg = ftanh(G.z), o2 = fsigm(G.w);
            c2 = fmaf(f2, c2, i2 * gg);
            float h = o2 * ftanh(c2);
            if (kk < HID) wh[bq * BSTR + 56 + kk] = __float2half(h);
        }
        if (wl == 0 && lane < 8 && u + 1 < SEQL)   // x[u+1] -> col 50
            wh[lane * BSTR + 50] = __float2half(sX[(8 * wg + lane) * SXS + (u + 1)]);

        asm volatile("bar.sync %0, %1;" :: "r"(1 + wg), "n"(NWG * 32) : "memory");
    }

    // ---- FC epilogue: h2[511] in group buf 1, cols 56..105 ----
    if (wl == 0 && lane < 8) {
        const __half* hh = gBH + BBUFH + lane * BSTR + 56;
        float acc = fc_b[0];
        #pragma unroll
        for (int k2 = 0; k2 < HID; k2++)
            acc = fmaf(__half2float(hh[k2]), fc_W[k2], acc);
        out[bg + 8 * wg + lane] = acc;
    }
}

extern "C" void kernel_launch(void* const* d_in, const int* in_sizes, int n_in,
                              void* d_out, int out_size)
{
    const float* x     = (const float*)d_in[0];
    const float* W_ih0 = (const float*)d_in[1];
    const float* W_hh0 = (const float*)d_in[2];
    const float* b_ih0 = (const float*)d_in[3];
    const float* b_hh0 = (const float*)d_in[4];
    const float* W_ih1 = (const float*)d_in[5];
    const float* W_hh1 = (const float*)d_in[6];
    const float* b_ih1 = (const float*)d_in[7];
    const float* b_hh1 = (const float*)d_in[8];
    const float* fc_W  = (const float*)d_in[9];
    const float* fc_b  = (const float*)d_in[10];
    float* out = (float*)d_out;

    const int smem_bytes = SMEM_FLOATS * (int)sizeof(float);
    cudaFuncSetAttribute(lstm2_kernel, cudaFuncAttributeMaxDynamicSharedMemorySize, smem_bytes);
    lstm2_kernel<<<NBATCH / BT, NTH, smem_bytes>>>(
        x, W_ih0, W_hh0, b_ih0, b_hh0,
        W_ih1, W_hh1, b_ih1, b_hh1, fc_W, fc_b, out);
}